// round 5
// baseline (speedup 1.0000x reference)
#include <cuda_runtime.h>
#include <cuda_bf16.h>
#include <cstdint>

// ---------------- problem constants ----------------
#define D_IN    4096
#define D_OUT   64
#define N_B     32
#define N_S     2048
#define N_LORA  16

#define TILE_M    256
#define NTHREADS  256
#define N_KCHUNK  (D_IN / 16)        // 256 k16 chunks
#define CPS       4                  // chunks per smem stage
#define N_STAGE   (N_KCHUNK / CPS)   // 64
#define STAGE_U4  (CPS * 256)        // 1024 uint4 per stage
#define STAGE_BYTES (STAGE_U4 * 16)  // 16 KB
#define SMEM_TOTAL  (2 * STAGE_BYTES)

// ---------------- weight scratch: fragment-layout bf16 hi/lo ----------------
// [lora][kchunk(256)][ntile(8)*32 + lane] -> uint4 {bhi0, bhi1, blo0, blo1}
// (b0 = k{2g,2g+1}, b1 = k{2g+8,2g+9} at col n, per mma.m16n8k16 B layout)
__device__ __align__(16) uint4 g_wfrag[(size_t)N_LORA * 256 * 256];

// ---------------- helpers ----------------
__device__ __forceinline__ uint32_t smem_u32(const void* p) {
    uint32_t a;
    asm("{ .reg .u64 t; cvta.to.shared.u64 t, %1; cvt.u32.u64 %0, t; }" : "=r"(a) : "l"(p));
    return a;
}

// pack two fp32 -> bf16x2, v0 in low 16 bits
__device__ __forceinline__ uint32_t bf16x2_pack(float v0, float v1) {
    uint32_t r;
    asm("cvt.rn.bf16x2.f32 %0, %1, %2;" : "=r"(r) : "f"(v1), "f"(v0));
    return r;
}

// fp32 pair -> bf16 hi pair + bf16 residual(lo) pair
__device__ __forceinline__ void split_pair(float v0, float v1, uint32_t& hi, uint32_t& lo) {
    hi = bf16x2_pack(v0, v1);
    float h0 = __uint_as_float(hi << 16);
    float h1 = __uint_as_float(hi & 0xFFFF0000u);
    lo = bf16x2_pack(v0 - h0, v1 - h1);
}

__device__ __forceinline__ void mma16816(float* c, const uint32_t* a, uint32_t b0, uint32_t b1) {
    asm volatile(
        "mma.sync.aligned.m16n8k16.row.col.f32.bf16.bf16.f32 "
        "{%0,%1,%2,%3}, {%4,%5,%6,%7}, {%8,%9}, {%0,%1,%2,%3};"
        : "+f"(c[0]), "+f"(c[1]), "+f"(c[2]), "+f"(c[3])
        : "r"(a[0]), "r"(a[1]), "r"(a[2]), "r"(a[3]), "r"(b0), "r"(b1));
}

__device__ __forceinline__ void cp_async16(uint32_t dst, const void* src) {
    asm volatile("cp.async.cg.shared.global [%0], [%1], 16;" :: "r"(dst), "l"(src) : "memory");
}

// ---------------- prep: weight[lora][k][n] fp32 -> fragment hi/lo scratch ----------------
// one block per (lora, kchunk): blockIdx.x = lora*256 + chunk
__global__ void __launch_bounds__(256)
lora_prep_kernel(const float* __restrict__ w) {
    __shared__ float sw[16][68];   // [k_local][n], padded
    const int t = threadIdx.x;
    // chunk tile = 16 k-rows x 64 n = contiguous 1024 floats
    const float* src = w + (size_t)blockIdx.x * 1024;
    float4 v = *(const float4*)(src + t * 4);
    const int kr = t >> 4, nc = (t & 15) * 4;
    sw[kr][nc + 0] = v.x; sw[kr][nc + 1] = v.y;
    sw[kr][nc + 2] = v.z; sw[kr][nc + 3] = v.w;
    __syncthreads();

    const int nt = t >> 5, l = t & 31;
    const int g = l & 3, nl = l >> 2;
    const int n = nt * 8 + nl;
    float v0 = sw[2 * g + 0][n], v1 = sw[2 * g + 1][n];
    float v2 = sw[2 * g + 8][n], v3 = sw[2 * g + 9][n];
    uint32_t h0, l0, h1, l1;
    split_pair(v0, v1, h0, l0);
    split_pair(v2, v3, h1, l1);
    g_wfrag[(size_t)blockIdx.x * 256 + t] = make_uint4(h0, h1, l0, l1);
}

// ---------------- main kernel ----------------
__device__ __forceinline__ void issue_stage(uint32_t sbase, const uint4* wsrc, int s, int t) {
    uint32_t dst = sbase + (uint32_t)(s & 1) * STAGE_BYTES + (uint32_t)t * 16;
    const uint4* src = wsrc + (size_t)s * STAGE_U4 + t;
    #pragma unroll
    for (int j = 0; j < CPS; ++j)
        cp_async16(dst + j * 4096, src + j * 256);
    asm volatile("cp.async.commit_group;" ::: "memory");
}

__global__ void __launch_bounds__(NTHREADS, 2)
lora_main_kernel(const float* __restrict__ x, const int* __restrict__ ids,
                 float* __restrict__ out) {
    extern __shared__ uint4 smem_buf[];
    const uint32_t sbase = smem_u32(smem_buf);
    const int t = threadIdx.x, wid = t >> 5, l = t & 31;
    const int g = l & 3, nl = l >> 2;

    const int b = blockIdx.x >> 3;
    const int mbase = (blockIdx.x & 7) * TILE_M;
    const int aid = __ldg(ids + b);
    const uint4* wsrc = g_wfrag + (size_t)aid * 256 * 256;
    // warp's 32 rows start here
    const float* xw = x + ((size_t)b * N_S + mbase + wid * 32) * D_IN;

    float acc[2][8][4];
    #pragma unroll
    for (int mt = 0; mt < 2; ++mt)
        #pragma unroll
        for (int nt = 0; nt < 8; ++nt)
            #pragma unroll
            for (int i = 0; i < 4; ++i)
                acc[mt][nt][i] = 0.0f;

    issue_stage(sbase, wsrc, 0, t);

    for (int s = 0; s < N_STAGE; ++s) {
        if (s + 1 < N_STAGE) {
            issue_stage(sbase, wsrc, s + 1, t);
            asm volatile("cp.async.wait_group 1;" ::: "memory");
        } else {
            asm volatile("cp.async.wait_group 0;" ::: "memory");
        }
        __syncthreads();
        const uint32_t stb = sbase + (uint32_t)(s & 1) * STAGE_BYTES;

        #pragma unroll
        for (int ci = 0; ci < CPS; ++ci) {
            const int k0 = s * (16 * CPS) + ci * 16;
            // ---- A: load fp32 direct from gmem, split to bf16 hi/lo frags ----
            uint32_t ah[2][4], al[2][4];
            #pragma unroll
            for (int mt = 0; mt < 2; ++mt) {
                const float* xr = xw + (size_t)(mt * 16 + nl) * D_IN + k0 + 2 * g;
                float2 f0 = *(const float2*)(xr);                 // (r,   k)
                float2 f1 = *(const float2*)(xr + 8);             // (r,   k+8)
                float2 f2 = *(const float2*)(xr + 8 * D_IN);      // (r+8, k)
                float2 f3 = *(const float2*)(xr + 8 * D_IN + 8);  // (r+8, k+8)
                split_pair(f0.x, f0.y, ah[mt][0], al[mt][0]);
                split_pair(f2.x, f2.y, ah[mt][1], al[mt][1]);
                split_pair(f1.x, f1.y, ah[mt][2], al[mt][2]);
                split_pair(f3.x, f3.y, ah[mt][3], al[mt][3]);
            }
            // ---- B from smem, 3-term mma per (mt, nt) ----
            #pragma unroll
            for (int nt = 0; nt < 8; ++nt) {
                uint32_t bh0, bh1, bl0, bl1;
                uint32_t a = stb + (uint32_t)(((ci * 8 + nt) * 32 + l) * 16);
                asm volatile("ld.shared.v4.b32 {%0,%1,%2,%3}, [%4];"
                             : "=r"(bh0), "=r"(bh1), "=r"(bl0), "=r"(bl1) : "r"(a));
                #pragma unroll
                for (int mt = 0; mt < 2; ++mt) {
                    mma16816(acc[mt][nt], ah[mt], bh0, bh1);  // hi * hi
                    mma16816(acc[mt][nt], ah[mt], bl0, bl1);  // hi * lo
                    mma16816(acc[mt][nt], al[mt], bh0, bh1);  // lo * hi
                }
            }
        }
        __syncthreads();
    }

    // ---- epilogue: fp32 accumulators -> out[b][row][n] ----
    #pragma unroll
    for (int mt = 0; mt < 2; ++mt) {
        const int row = mbase + wid * 32 + mt * 16 + nl;
        float* o = out + ((size_t)b * N_S + row) * D_OUT + 2 * g;
        #pragma unroll
        for (int nt = 0; nt < 8; ++nt) {
            *(float2*)(o + nt * 8)             = make_float2(acc[mt][nt][0], acc[mt][nt][1]);
            *(float2*)(o + nt * 8 + 8 * D_OUT) = make_float2(acc[mt][nt][2], acc[mt][nt][3]);
        }
    }
}

// ---------------- launch ----------------
extern "C" void kernel_launch(void* const* d_in, const int* in_sizes, int n_in,
                              void* d_out, int out_size) {
    const float* x  = (const float*)d_in[0];
    const int* ids  = (const int*)d_in[1];
    const float* w  = (const float*)d_in[2];
    float* out      = (float*)d_out;

    lora_prep_kernel<<<N_LORA * 256, 256>>>(w);
    lora_main_kernel<<<N_B * (N_S / TILE_M), NTHREADS, SMEM_TOTAL>>>(x, ids, out);
}